// round 9
// baseline (speedup 1.0000x reference)
#include <cuda_runtime.h>

// score[e] = sum_d h[src[e], d] * h[dst[e], d]
// h: [100000, 32] fp32 ; src/dst: int32 [E] ; out: fp32 [E]
//
// 16 lanes per row (LDG.64 float2 gathers): each warp-level gather
// instruction touches only 2 distinct 128B lines (vs 4 with the float4/8-lane
// scheme). Within-LDG line replays (~2.07 cyc/line) were the measured binder
// at 26.6us; halving lines-per-inst targets that directly.
//
// Group = 16 lanes, 4 edges per pass:
//  - 2x int4 broadcast index loads
//  - 8 independent float2 gathers (MLP=8)
//  - value-halving reduce (5 shuffles / 4 edges); edge (2*b3+b2) lands on
//    lanes l%4==0 -> contiguous predicated store of 4 floats per group

static constexpr int D = 32;
static constexpr int EPG = 4;            // edges per 16-lane group
static constexpr unsigned FULL = 0xFFFFFFFFu;

__device__ __forceinline__ float2 grow2(const float* __restrict__ h, int idx, int i) {
    // lane i of the 16-lane group loads floats [2i, 2i+1] of row idx
    return reinterpret_cast<const float2*>(h + (long long)idx * D)[i];
}

__device__ __forceinline__ float pdot(float2 a, float2 b) {
    return a.x * b.x + a.y * b.y;
}

__global__ __launch_bounds__(256, 7) void edge_dot_kernel(
    const float* __restrict__ h,
    const int* __restrict__ src,
    const int* __restrict__ dst,
    float* __restrict__ out,
    int E)
{
    int gid = blockIdx.x * blockDim.x + threadIdx.x;
    int g = gid >> 4;                 // 16-lane group index
    int i = gid & 15;                 // lane within group
    long long e0 = (long long)g * EPG;
    if (e0 >= E) return;

    if (e0 + EPG <= E) {
        int4 s4 = *reinterpret_cast<const int4*>(src + e0);   // broadcast
        int4 d4 = *reinterpret_cast<const int4*>(dst + e0);   // broadcast

        // 8 independent float2 gathers (each warp-inst touches 2 lines)
        float2 a0 = grow2(h, s4.x, i);
        float2 b0 = grow2(h, d4.x, i);
        float2 a1 = grow2(h, s4.y, i);
        float2 b1 = grow2(h, d4.y, i);
        float2 a2 = grow2(h, s4.z, i);
        float2 b2 = grow2(h, d4.z, i);
        float2 a3 = grow2(h, s4.w, i);
        float2 b3 = grow2(h, d4.w, i);

        float p0 = pdot(a0, b0);
        float p1 = pdot(a1, b1);
        float p2 = pdot(a2, b2);
        float p3 = pdot(a3, b3);

        // --- value-halving reduction over 16 lanes (5 shuffles / 4 edges) ---
        // level xor-8: 4 values -> 2 (lanes b3=0 keep edges {0,1}, b3=1 keep {2,3})
        bool h8 = (i & 8) != 0;
        float u0 = h8 ? p0 : p2;  float v0 = __shfl_xor_sync(FULL, u0, 8);
        float u1 = h8 ? p1 : p3;  float v1 = __shfl_xor_sync(FULL, u1, 8);
        float q0 = (h8 ? p2 : p0) + v0;   // edge (2*b3 + 0) partial
        float q1 = (h8 ? p3 : p1) + v1;   // edge (2*b3 + 1) partial

        // level xor-4: 2 values -> 1 (b2 picks within the pair)
        bool h4 = (i & 4) != 0;
        float u2 = h4 ? q0 : q1;  float v2 = __shfl_xor_sync(FULL, u2, 4);
        float r = (h4 ? q1 : q0) + v2;    // edge (2*b3 + b2) partial

        // complete the lane sum (bits 1,0)
        r += __shfl_xor_sync(FULL, r, 2);
        r += __shfl_xor_sync(FULL, r, 1);

        // lane l (l%4==0) holds the full sum for edge e0 + 2*b3 + b2
        if ((i & 3) == 0) {
            int k = ((i >> 3) & 1) * 2 + ((i >> 2) & 1);
            out[e0 + k] = r;
        }
    } else {
        // remainder (E not divisible by 4)
        for (long long e = e0; e < E; ++e) {
            float2 a = grow2(h, src[e], i);
            float2 b = grow2(h, dst[e], i);
            float p = pdot(a, b);
            p += __shfl_xor_sync(FULL, p, 1);
            p += __shfl_xor_sync(FULL, p, 2);
            p += __shfl_xor_sync(FULL, p, 4);
            p += __shfl_xor_sync(FULL, p, 8);
            if (i == 0) out[e] = p;
        }
    }
}

extern "C" void kernel_launch(void* const* d_in, const int* in_sizes, int n_in,
                              void* d_out, int out_size)
{
    const float* h   = (const float*)d_in[0];
    const int*   src = (const int*)d_in[1];
    const int*   dst = (const int*)d_in[2];
    float*       out = (float*)d_out;

    int E = in_sizes[1];
    long long groups = ((long long)E + EPG - 1) / EPG;
    long long total_threads = groups * 16;
    int block = 256;
    int grid = (int)((total_threads + block - 1) / block);

    edge_dot_kernel<<<grid, block>>>(h, src, dst, out, E);
}

// round 10
// speedup vs baseline: 1.2668x; 1.2668x over previous
#include <cuda_runtime.h>

// score[e] = sum_d h[src[e], d] * h[dst[e], d]
// h: [100000, 32] fp32 ; src/dst: int32 [E] ; out: fp32 [E]
//
// Proven-best structure (R5): 8 lanes per group, 4 edges per group.
//  - int4 broadcast index loads (4 src + 4 dst idx per group)
//  - 8 independent float4 gathers (MLP=8; each group touches exactly one
//    128B line per gathered row)
//  - value-halving shuffle reduction: 4 shuffles for 4 edge-sums
//  - results land on lanes 0,2,4,6 -> dense coalesced store
// This round: block 128 (16 blocks/SM, same 2048-thread occupancy) to cut
// per-CTA spread / wave-tail from cross-CTA L1tex-queue contention.

static constexpr int D = 32;
static constexpr int EDGES_PER_GROUP = 4;
static constexpr unsigned FULL = 0xFFFFFFFFu;

__device__ __forceinline__ float dot4(float4 a, float4 b) {
    return a.x * b.x + a.y * b.y + a.z * b.z + a.w * b.w;
}

__device__ __forceinline__ float red8(float p) {
    p += __shfl_xor_sync(FULL, p, 1);
    p += __shfl_xor_sync(FULL, p, 2);
    p += __shfl_xor_sync(FULL, p, 4);
    return p;
}

__global__ __launch_bounds__(128, 16) void edge_dot_kernel(
    const float* __restrict__ h,
    const int* __restrict__ src,
    const int* __restrict__ dst,
    float* __restrict__ out,
    int E)
{
    int gid = blockIdx.x * blockDim.x + threadIdx.x;
    int g = gid >> 3;                 // 8-lane group index
    int i = gid & 7;                  // lane within group
    long long e0 = (long long)g * EDGES_PER_GROUP;
    if (e0 >= E) return;

    if (e0 + EDGES_PER_GROUP <= E) {
        int4 s4 = *reinterpret_cast<const int4*>(src + e0);
        int4 d4 = *reinterpret_cast<const int4*>(dst + e0);

        // 8 independent gathers in flight
        float4 a0 = reinterpret_cast<const float4*>(h + (long long)s4.x * D)[i];
        float4 b0 = reinterpret_cast<const float4*>(h + (long long)d4.x * D)[i];
        float4 a1 = reinterpret_cast<const float4*>(h + (long long)s4.y * D)[i];
        float4 b1 = reinterpret_cast<const float4*>(h + (long long)d4.y * D)[i];
        float4 a2 = reinterpret_cast<const float4*>(h + (long long)s4.z * D)[i];
        float4 b2 = reinterpret_cast<const float4*>(h + (long long)d4.z * D)[i];
        float4 a3 = reinterpret_cast<const float4*>(h + (long long)s4.w * D)[i];
        float4 b3 = reinterpret_cast<const float4*>(h + (long long)d4.w * D)[i];

        float p0 = dot4(a0, b0);
        float p1 = dot4(a1, b1);
        float p2 = dot4(a2, b2);
        float p3 = dot4(a3, b3);

        // --- value-halving reduction over the 8-lane group (4 shuffles) ---
        bool hi4 = (i & 4) != 0;
        float ua = hi4 ? p0 : p2;
        float va = __shfl_xor_sync(FULL, ua, 4);
        float ub = hi4 ? p1 : p3;
        float vb = __shfl_xor_sync(FULL, ub, 4);
        float q0 = (hi4 ? p2 : p0) + va;
        float q1 = (hi4 ? p3 : p1) + vb;

        bool hi2 = (i & 2) != 0;
        float uc = hi2 ? q0 : q1;
        float vc = __shfl_xor_sync(FULL, uc, 2);
        float r = (hi2 ? q1 : q0) + vc;

        r += __shfl_xor_sync(FULL, r, 1);

        // lane 2k holds the full sum for edge e0+k (k = i>>1)
        if ((i & 1) == 0) out[e0 + (i >> 1)] = r;
    } else {
        // remainder (E not divisible by 4)
        for (long long e = e0; e < E; ++e) {
            int s = src[e];
            int d = dst[e];
            float4 a = reinterpret_cast<const float4*>(h + (long long)s * D)[i];
            float4 b = reinterpret_cast<const float4*>(h + (long long)d * D)[i];
            float p = red8(dot4(a, b));
            if (i == 0) out[e] = p;
        }
    }
}

extern "C" void kernel_launch(void* const* d_in, const int* in_sizes, int n_in,
                              void* d_out, int out_size)
{
    const float* h   = (const float*)d_in[0];
    const int*   src = (const int*)d_in[1];
    const int*   dst = (const int*)d_in[2];
    float*       out = (float*)d_out;

    int E = in_sizes[1];
    long long groups = ((long long)E + EDGES_PER_GROUP - 1) / EDGES_PER_GROUP;
    long long total_threads = groups * 8;
    int block = 128;
    int grid = (int)((total_threads + block - 1) / block);

    edge_dot_kernel<<<grid, block>>>(h, src, dst, out, E);
}